// round 8
// baseline (speedup 1.0000x reference)
#include <cuda_runtime.h>

typedef unsigned long long u64;

// ---------------- scratch (static device globals: allocation-free) ----------------
__device__ __align__(128) float g_k1t[4*8*4096*16];    // [b,h,s,d] level-1 keys
__device__ __align__(128) float g_v1t[4*8*4096*16];
__device__ __align__(128) float g_k0t[4*8*16384*16];   // [b,h,s,d] level-2 keys
__device__ __align__(128) float g_v0t[4*8*16384*16];
__device__ __align__(128) float g_k2t[4*8*1024*16];    // [b,h,s,d] level-0 keys
__device__ __align__(128) float g_v2t[4*8*1024*16];
__device__ __align__(128) float g_msg0[4*8*1024*16];       // [b,h,l,d]
__device__ __align__(128) float g_msg1[4*8*1024*4*16];     // [b,h,l,t,d]
__device__ __align__(128) float g_msg2[4*8*4096*4*16];     // [b,h,l,t,d]
__device__ int   g_idx0[4*8*1024*16];         // [b,h,l,16]
__device__ int   g_idx1[4*8*4096*8];          // [b,h,pix,8]

// ---------------- packed f32x2 helpers ----------------
__device__ __forceinline__ u64 pack2(float a, float b) {
    u64 r; asm("mov.b64 %0,{%1,%2};" : "=l"(r) : "f"(a), "f"(b)); return r;
}
__device__ __forceinline__ void unpack2(u64 v, float& a, float& b) {
    asm("mov.b64 {%0,%1},%2;" : "=f"(a), "=f"(b) : "l"(v));
}
__device__ __forceinline__ u64 ffma2(u64 a, u64 b, u64 c) {
    u64 d; asm("fma.rn.f32x2 %0,%1,%2,%3;" : "=l"(d) : "l"(a), "l"(b), "l"(c)); return d;
}
__device__ __forceinline__ u64 mul2(u64 a, u64 b) {
    u64 d; asm("mul.rn.f32x2 %0,%1,%2;" : "=l"(d) : "l"(a), "l"(b)); return d;
}
__device__ __forceinline__ u64 add2(u64 a, u64 b) {
    u64 d; asm("add.rn.f32x2 %0,%1,%2;" : "=l"(d) : "l"(a), "l"(b)); return d;
}

// load 16 consecutive floats (64B) as 8 packed f32x2 (LDG.128 x4, no MOVs)
__device__ __forceinline__ void ld8(u64 (&r)[8], const float* p) {
    const ulonglong2* pp = reinterpret_cast<const ulonglong2*>(p);
    ulonglong2 a = pp[0], b = pp[1], c = pp[2], d = pp[3];
    r[0]=a.x; r[1]=a.y; r[2]=b.x; r[3]=b.y; r[4]=c.x; r[5]=c.y; r[6]=d.x; r[7]=d.y;
}

__device__ __forceinline__ float dot16u(const u64 (&qr)[8], const u64 (&k)[8]) {
    u64 d0 = mul2(qr[0],k[0]), d1 = mul2(qr[1],k[1]);
    u64 d2 = mul2(qr[2],k[2]), d3 = mul2(qr[3],k[3]);
    d0 = ffma2(qr[4],k[4],d0); d1 = ffma2(qr[5],k[5],d1);
    d2 = ffma2(qr[6],k[6],d2); d3 = ffma2(qr[7],k[7],d3);
    u64 e0 = add2(d0,d1), e1 = add2(d2,d3), e2 = add2(e0,e1);
    float lo, hi; unpack2(e2, lo, hi);
    return lo + hi;
}

__device__ __forceinline__ void acc_fma_u(u64 (&acc)[8], u64 e2, const u64 (&v)[8]) {
    #pragma unroll
    for (int i = 0; i < 8; ++i) acc[i] = ffma2(e2, v[i], acc[i]);
}
__device__ __forceinline__ void acc_rescale_add_u(u64 (&acc)[8], u64 c2, const u64 (&v)[8]) {
    #pragma unroll
    for (int i = 0; i < 8; ++i) acc[i] = ffma2(c2, acc[i], v[i]);
}

template<int K>
__device__ __forceinline__ void topk_insert(float (&tv)[K], int (&ti)[K], float sc, int id) {
    // caller guarantees sc > tv[K-1]; strict-> preserves jax lower-index-first ties
    bool done = false;
    #pragma unroll
    for (int i = K-1; i >= 1; --i) {
        if (!done) {
            if (sc > tv[i-1]) { tv[i] = tv[i-1]; ti[i] = ti[i-1]; }
            else              { tv[i] = sc; ti[i] = id; done = true; }
        }
    }
    if (!done) { tv[0] = sc; ti[0] = id; }
}

// merge insert with explicit idx tie-break (lower idx wins)
__device__ __forceinline__ void topk_insert_tie(float (&tv)[16], int (&ti)[16], float sc, int id) {
    bool done = false;
    #pragma unroll
    for (int i = 15; i >= 1; --i) {
        if (!done) {
            bool beats = (sc > tv[i-1]) || (sc == tv[i-1] && id < ti[i-1]);
            if (beats) { tv[i] = tv[i-1]; ti[i] = ti[i-1]; }
            else       { tv[i] = sc; ti[i] = id; done = true; }
        }
    }
    if (!done) { tv[0] = sc; ti[0] = id; }
}

__device__ __forceinline__ void store_msg(float* mo, const u64 (&acc)[8], float inv) {
    #pragma unroll
    for (int i = 0; i < 8; ++i) {
        float lo, hi; unpack2(acc[i], lo, hi);
        mo[2*i]   = lo * inv;
        mo[2*i+1] = hi * inv;
    }
}

// ---------------- transpose: NCHW [b,128,S] -> [b,h,S,16] ----------------
__global__ __launch_bounds__(256) void k_transpose(const float* __restrict__ in, int S, int which) {
    float* out = (which == 0) ? g_k1t : (which == 1) ? g_v1t :
                 (which == 2) ? g_k0t : (which == 3) ? g_v0t :
                 (which == 4) ? g_k2t : g_v2t;
    __shared__ float sm[128*17];  // [sl][dd], stride 17
    const int b = blockIdx.z, h = blockIdx.y;
    const int s0 = blockIdx.x * 128;
    const int tid = threadIdx.x;
    const float* ib = in + ((size_t)(b*8 + h) * 16) * S + s0;
    #pragma unroll
    for (int k = 0; k < 8; ++k) {
        int lin = tid + k*256;
        int dd = lin >> 7, sl = lin & 127;
        sm[sl*17 + dd] = ib[dd*S + sl];
    }
    __syncthreads();
    float* ob = out + ((size_t)(b*8 + h) * S + s0) * 16;
    #pragma unroll
    for (int k = 0; k < 8; ++k) {
        int lin = tid + k*256;
        int sl = lin >> 4, dd = lin & 15;
        ob[lin] = sm[sl*17 + dd];
    }
}

// ---------------- level 0: full attention on 32x32, split-K x4, top-16 ----------------
__global__ __launch_bounds__(128) void k_level0(const float* __restrict__ q2) {
    __shared__ float smv[32][4][16];
    __shared__ int   smi[32][4][16];
    const int tid = threadIdx.x;
    const int bh = blockIdx.z * 8 + blockIdx.y;
    const int qloc = tid >> 2;                 // 0..31 query within block
    const int s = blockIdx.x * 32 + qloc;
    const int t = tid & 3;                     // key-chunk within quad

    const float* qb = q2 + (size_t)bh * 16 * 1024;
    u64 qr[8];
    #pragma unroll
    for (int i = 0; i < 8; ++i)
        qr[i] = pack2(qb[(2*i)*1024 + s], qb[(2*i+1)*1024 + s]);

    const float* kb = g_k2t + (size_t)bh * 1024 * 16 + (size_t)t * 256 * 16;
    const float* vb = g_v2t + (size_t)bh * 1024 * 16 + (size_t)t * 256 * 16;

    u64 acc[8];
    #pragma unroll
    for (int i = 0; i < 8; ++i) acc[i] = pack2(0.f, 0.f);
    float m = -1e30f, Z = 0.f;
    float topv[16]; int topi[16];
    #pragma unroll
    for (int i = 0; i < 16; ++i) { topv[i] = -1e30f; topi[i] = 0; }

    const int base = t * 256;
    for (int j = 0; j < 256; ++j) {
        u64 k8[8]; ld8(k8, kb + (size_t)j*16);
        float sc = dot16u(qr, k8) * 0.25f;
        u64 v8[8]; ld8(v8, vb + (size_t)j*16);
        if (sc > topv[15]) topk_insert<16>(topv, topi, sc, base + j);
        if (sc > m) {
            float cor = __expf(m - sc);
            m = sc;
            Z = Z * cor + 1.f;
            acc_rescale_add_u(acc, pack2(cor, cor), v8);
        } else {
            float e = __expf(sc - m);
            Z += e;
            acc_fma_u(acc, pack2(e, e), v8);
        }
    }

    // ---- quad reduce of online-softmax state ----
    float mq = m;
    mq = fmaxf(mq, __shfl_xor_sync(0xffffffffu, mq, 1));
    mq = fmaxf(mq, __shfl_xor_sync(0xffffffffu, mq, 2));
    float scale = __expf(m - mq);
    Z *= scale;
    u64 s2 = pack2(scale, scale);
    #pragma unroll
    for (int i = 0; i < 8; ++i) acc[i] = mul2(acc[i], s2);
    Z += __shfl_xor_sync(0xffffffffu, Z, 1);
    Z += __shfl_xor_sync(0xffffffffu, Z, 2);
    #pragma unroll
    for (int i = 0; i < 8; ++i) acc[i] = add2(acc[i], __shfl_xor_sync(0xffffffffu, acc[i], 1));
    #pragma unroll
    for (int i = 0; i < 8; ++i) acc[i] = add2(acc[i], __shfl_xor_sync(0xffffffffu, acc[i], 2));

    // ---- top-16 merge across the 4 chunks ----
    #pragma unroll
    for (int r = 0; r < 16; ++r) { smv[qloc][t][r] = topv[r]; smi[qloc][t][r] = topi[r]; }
    __syncwarp();

    if (t == 0) {
        float tv[16]; int ti[16];
        #pragma unroll
        for (int i = 0; i < 16; ++i) { tv[i] = -1e30f; ti[i] = 0x7fffffff; }
        for (int t2 = 0; t2 < 4; ++t2) {
            for (int r = 0; r < 16; ++r) {
                float v = smv[qloc][t2][r]; int id = smi[qloc][t2][r];
                bool beats = (v > tv[15]) || (v == tv[15] && id < ti[15]);
                if (beats) topk_insert_tie(tv, ti, v, id);
                else break;   // lists sorted desc (tie: idx asc) -> monotone
            }
        }
        float inv = 1.f / Z;
        store_msg(g_msg0 + (size_t)(bh*1024 + s)*16, acc, inv);
        int* io = g_idx0 + (size_t)(bh*1024 + s)*16;
        #pragma unroll
        for (int w = 0; w < 16; ++w) io[w] = ti[w];
    }
}

// ---------------- level 1: 64 gathered candidates per query, top-8 ----------------
__global__ __launch_bounds__(128) void k_level1(const float* __restrict__ q1) {
    const int tid = threadIdx.x;
    const int bh = blockIdx.z * 8 + blockIdx.y;
    const int l = blockIdx.x * 32 + (tid >> 2);
    const int t = tid & 3;
    const int ly = l >> 5, lx = l & 31;
    const int y1 = 2*ly + (t >> 1), x1 = 2*lx + (t & 1);
    const int s1 = y1*64 + x1;

    const float* qb = q1 + (size_t)bh * 16 * 4096;
    u64 qr[8];
    #pragma unroll
    for (int i = 0; i < 8; ++i)
        qr[i] = pack2(qb[(2*i)*4096 + s1], qb[(2*i+1)*4096 + s1]);

    const int* ib = g_idx0 + (size_t)(bh*1024 + l)*16;
    const float* kb = g_k1t + (size_t)bh * 4096 * 16;
    const float* vb = g_v1t + (size_t)bh * 4096 * 16;

    u64 acc[8];
    #pragma unroll
    for (int i = 0; i < 8; ++i) acc[i] = pack2(0.f, 0.f);
    float m = -1e30f, Z = 0.f;
    float topv[8]; int topi[8];
    #pragma unroll
    for (int i = 0; i < 8; ++i) { topv[i] = -1e30f; topi[i] = 0; }

    for (int w = 0; w < 16; ++w) {
        int p = ib[w];
        int py = (p >> 5) << 1, px = (p & 31) << 1;
        #pragma unroll
        for (int c = 0; c < 4; ++c) {
            int cand = (py + (c >> 1))*64 + px + (c & 1);
            u64 k8[8]; ld8(k8, kb + (size_t)cand*16);
            float sc = dot16u(qr, k8) * 0.25f;
            u64 v8[8]; ld8(v8, vb + (size_t)cand*16);
            if (sc > topv[7]) topk_insert<8>(topv, topi, sc, cand);
            if (sc > m) {
                float cor = __expf(m - sc);
                m = sc;
                Z = Z * cor + 1.f;
                acc_rescale_add_u(acc, pack2(cor, cor), v8);
            } else {
                float e = __expf(sc - m);
                Z += e;
                acc_fma_u(acc, pack2(e, e), v8);
            }
        }
    }
    float inv = 1.f / Z;
    store_msg(g_msg1 + (size_t)((bh*1024 + l)*4 + t)*16, acc, inv);
    int* io = g_idx1 + (size_t)(bh*4096 + s1)*8;
    #pragma unroll
    for (int w = 0; w < 8; ++w) io[w] = topi[w];
}

// ---------------- level 2: 32 gathered candidates per query (no top-k) ----------------
__global__ __launch_bounds__(128) void k_level2(const float* __restrict__ q0) {
    const int tid = threadIdx.x;
    const int bh = blockIdx.z * 8 + blockIdx.y;
    const int l = blockIdx.x * 32 + (tid >> 2);
    const int t = tid & 3;
    const int ly = l >> 6, lx = l & 63;
    const int y = 2*ly + (t >> 1), x = 2*lx + (t & 1);
    const int s0 = y*128 + x;

    const float* qb = q0 + (size_t)bh * 16 * 16384;
    u64 qr[8];
    #pragma unroll
    for (int i = 0; i < 8; ++i)
        qr[i] = pack2(qb[(2*i)*16384 + s0], qb[(2*i+1)*16384 + s0]);

    const int* ib = g_idx1 + (size_t)(bh*4096 + l)*8;
    const float* kb = g_k0t + (size_t)bh * 16384 * 16;
    const float* vb = g_v0t + (size_t)bh * 16384 * 16;

    u64 acc[8];
    #pragma unroll
    for (int i = 0; i < 8; ++i) acc[i] = pack2(0.f, 0.f);
    float m = -1e30f, Z = 0.f;

    for (int w = 0; w < 8; ++w) {
        int p = ib[w];
        int py = (p >> 6) << 1, px = (p & 63) << 1;
        #pragma unroll
        for (int c = 0; c < 4; ++c) {
            int cand = (py + (c >> 1))*128 + px + (c & 1);
            u64 k8[8]; ld8(k8, kb + (size_t)cand*16);
            float sc = dot16u(qr, k8) * 0.25f;
            u64 v8[8]; ld8(v8, vb + (size_t)cand*16);
            if (sc > m) {
                float cor = __expf(m - sc);
                m = sc;
                Z = Z * cor + 1.f;
                acc_rescale_add_u(acc, pack2(cor, cor), v8);
            } else {
                float e = __expf(sc - m);
                Z += e;
                acc_fma_u(acc, pack2(e, e), v8);
            }
        }
    }
    float inv = 1.f / Z;
    store_msg(g_msg2 + (size_t)((bh*4096 + l)*4 + t)*16, acc, inv);
}

// ---------------- combine: weighted pyramid sum ----------------
__global__ __launch_bounds__(256) void k_combine(const float* __restrict__ wt, float* __restrict__ out) {
    const int gid = blockIdx.x * 256 + threadIdx.x;  // (b, s, h)
    float w0r = wt[0], w1r = wt[1], w2r = wt[2];
    float mx = fmaxf(w0r, fmaxf(w1r, w2r));
    float e0 = expf(w0r - mx), e1 = expf(w1r - mx), e2 = expf(w2r - mx);
    float inv = 1.f / (e0 + e1 + e2);
    float w0 = e0*inv, w1 = e1*inv, w2 = e2*inv;

    const int h = gid & 7;
    const int s = (gid >> 3) & 16383;
    const int b = gid >> 17;
    const int y = s >> 7, x = s & 127;
    const int bh = b*8 + h;
    const int l0 = (y >> 2)*32 + (x >> 2);
    const int t1 = (((y >> 1) & 1) << 1) | ((x >> 1) & 1);
    const int l2 = (y >> 1)*64 + (x >> 1);
    const int t2 = ((y & 1) << 1) | (x & 1);

    const float4* p0 = reinterpret_cast<const float4*>(g_msg0 + (size_t)(bh*1024 + l0)*16);
    const float4* p1 = reinterpret_cast<const float4*>(g_msg1 + (size_t)((bh*1024 + l0)*4 + t1)*16);
    const float4* p2 = reinterpret_cast<const float4*>(g_msg2 + (size_t)((bh*4096 + l2)*4 + t2)*16);
    float4* po = reinterpret_cast<float4*>(out + (size_t)gid*16);
    #pragma unroll
    for (int i = 0; i < 4; ++i) {
        float4 a = p0[i], c = p1[i], d = p2[i];
        float4 r;
        r.x = w0*a.x + w1*c.x + w2*d.x;
        r.y = w0*a.y + w1*c.y + w2*d.y;
        r.z = w0*a.z + w1*c.z + w2*d.z;
        r.w = w0*a.w + w1*c.w + w2*d.w;
        po[i] = r;
    }
}

// ---------------- launcher ----------------
extern "C" void kernel_launch(void* const* d_in, const int* in_sizes, int n_in,
                              void* d_out, int out_size) {
    (void)in_sizes; (void)n_in; (void)out_size;
    const float* q0 = (const float*)d_in[0];
    const float* q1 = (const float*)d_in[1];
    const float* q2 = (const float*)d_in[2];
    const float* k0 = (const float*)d_in[3];
    const float* k1 = (const float*)d_in[4];
    const float* k2 = (const float*)d_in[5];
    const float* v0 = (const float*)d_in[6];
    const float* v1 = (const float*)d_in[7];
    const float* v2 = (const float*)d_in[8];
    const float* wt = (const float*)d_in[9];
    float* out = (float*)d_out;

    k_transpose<<<dim3(8,  8, 4), 256>>>(k2, 1024, 4);
    k_transpose<<<dim3(8,  8, 4), 256>>>(v2, 1024, 5);
    k_transpose<<<dim3(32, 8, 4), 256>>>(k1, 4096, 0);
    k_transpose<<<dim3(32, 8, 4), 256>>>(v1, 4096, 1);
    k_transpose<<<dim3(128, 8, 4), 256>>>(k0, 16384, 2);
    k_transpose<<<dim3(128, 8, 4), 256>>>(v0, 16384, 3);
    k_level0<<<dim3(32, 8, 4), 128>>>(q2);
    k_level1<<<dim3(32, 8, 4), 128>>>(q1);
    k_level2<<<dim3(128, 8, 4), 128>>>(q0);
    k_combine<<<2048, 256>>>(wt, out);
}